// round 4
// baseline (speedup 1.0000x reference)
#include <cuda_runtime.h>

#define BS_     128
#define NF_     4
#define P_LO_   1024
#define P_HI_   16384
#define K_      9
#define NC_     36
#define TILE_   1024                 // hi points per CTA
#define NTILES_ (P_HI_ / TILE_)      // 16
#define THREADS_ 256                 // 4 points per thread

// Scratch for class grouping (allocation-free: __device__ globals).
__device__ int g_cls_count[NC_];
__device__ int g_cls_list[NC_][BS_];

// Deterministic prepass: thread c collects all samples of class c in batch order.
__global__ void build_lists_kernel(const int* __restrict__ cls_ids) {
    int c = threadIdx.x;
    if (c < NC_) {
        int n = 0;
        #pragma unroll 4
        for (int b = 0; b < BS_; b++) {
            if (cls_ids[b] == c) g_cls_list[c][n++] = b;
        }
        g_cls_count[c] = n;
    }
}

// One CTA per (class, feature, hi-tile). Weights / neighbor indices / bias_high
// for the tile live in registers; loop over the class's samples reusing them.
__global__ void __launch_bounds__(THREADS_, 2)
upsample_kernel(const float* __restrict__ x,
                const int*   __restrict__ nbr,
                const float* __restrict__ wmap,
                const float* __restrict__ blo,
                const float* __restrict__ bhi,
                float*       __restrict__ out)
{
    __shared__ float y_sh[P_LO_];

    const int tile = blockIdx.x;
    const int f    = blockIdx.y;
    const int c    = blockIdx.z;
    const int n    = g_cls_count[c];
    if (n == 0) return;                       // block-uniform exit (no syncs yet)

    const int tid = threadIdx.x;
    const int p0  = tile * TILE_ + tid * 4;   // first of this thread's 4 hi points

    // ---- tile-constant loads (once per CTA, fully coalesced float4/int4) ----
    // weight_map[c][f][p0..p0+3][0..8] : 36 consecutive floats, 16B aligned.
    const float4* wp = reinterpret_cast<const float4*>(
        wmap + (((size_t)c * NF_ + f) * P_HI_ + (size_t)p0) * K_);
    float wv[36];
    #pragma unroll
    for (int i = 0; i < 9; i++) {
        float4 v = wp[i];
        wv[i * 4 + 0] = v.x; wv[i * 4 + 1] = v.y;
        wv[i * 4 + 2] = v.z; wv[i * 4 + 3] = v.w;
    }

    // neighbor_indices[p0..p0+3][0..8] : 36 consecutive ints, 16B aligned.
    const int4* ip = reinterpret_cast<const int4*>(nbr + (size_t)p0 * K_);
    int nb[36];
    #pragma unroll
    for (int i = 0; i < 9; i++) {
        int4 v = ip[i];
        nb[i * 4 + 0] = v.x; nb[i * 4 + 1] = v.y;
        nb[i * 4 + 2] = v.z; nb[i * 4 + 3] = v.w;
    }

    // bias_high[c][f][p0..p0+3]
    float4 bh = *reinterpret_cast<const float4*>(
        bhi + ((size_t)c * NF_ + f) * P_HI_ + p0);
    float bhv[4] = { bh.x, bh.y, bh.z, bh.w };

    const float4* blo4 = reinterpret_cast<const float4*>(
        blo + ((size_t)c * NF_ + f) * P_LO_);

    // ---- per-sample loop ----
    for (int s = 0; s < n; s++) {
        const int b = g_cls_list[c][s];

        // Stage y_low - bias_low into shared: one float4 per thread covers P_LO.
        const float4* xp = reinterpret_cast<const float4*>(
            x + (size_t)b * (NF_ * P_LO_) + (size_t)f * P_LO_);
        float4 xv = xp[tid];
        float4 bv = blo4[tid];
        reinterpret_cast<float4*>(y_sh)[tid] =
            make_float4(xv.x - bv.x, xv.y - bv.y, xv.z - bv.z, xv.w - bv.w);
        __syncthreads();

        float4 res;
        float* rp = reinterpret_cast<float*>(&res);
        #pragma unroll
        for (int j = 0; j < 4; j++) {
            float sum = bhv[j];
            #pragma unroll
            for (int k = 0; k < K_; k++)
                sum = fmaf(wv[j * K_ + k], y_sh[nb[j * K_ + k]], sum);
            rp[j] = sum;
        }

        *reinterpret_cast<float4*>(
            out + ((size_t)b * NF_ + f) * P_HI_ + p0) = res;

        __syncthreads();   // protect y_sh before next sample's staging
    }
}

extern "C" void kernel_launch(void* const* d_in, const int* in_sizes, int n_in,
                              void* d_out, int out_size) {
    const float* x    = (const float*)d_in[0];   // (BS, NF*P_LO) f32
    const int*   cls  = (const int*)  d_in[1];   // (BS,) i32
    const int*   nbr  = (const int*)  d_in[2];   // (P_HI, K) i32
    const float* wmap = (const float*)d_in[3];   // (NC, NF, P_HI, K) f32
    const float* blo  = (const float*)d_in[4];   // (NC, NF, P_LO) f32
    const float* bhi  = (const float*)d_in[5];   // (NC, NF, P_HI) f32
    float* out = (float*)d_out;                  // (BS, NF, P_HI) f32

    build_lists_kernel<<<1, 64>>>(cls);
    dim3 grid(NTILES_, NF_, NC_);
    upsample_kernel<<<grid, THREADS_>>>(x, nbr, wmap, blo, bhi, out);
}

// round 6
// speedup vs baseline: 1.1164x; 1.1164x over previous
#include <cuda_runtime.h>

#define BS_      128
#define NF_      4
#define P_LO_    1024
#define P_HI_    16384
#define K_       9
#define NC_      36
#define PPT_     2                    // hi points per thread
#define THREADS_ 256
#define TILE_    (THREADS_ * PPT_)    // 512
#define NTILES_  (P_HI_ / TILE_)      // 32

// Scratch for class grouping (allocation-free: __device__ globals).
__device__ int g_cls_count[NC_];
__device__ int g_cls_list[NC_][BS_];

// Deterministic prepass: one warp per class, ballot+popc prefix keeps batch order.
__global__ void build_lists_kernel(const int* __restrict__ cls_ids) {
    int w    = (blockIdx.x * blockDim.x + threadIdx.x) >> 5;   // class id
    int lane = threadIdx.x & 31;
    if (w >= NC_) return;
    int base = 0;
    #pragma unroll
    for (int chunk = 0; chunk < BS_ / 32; chunk++) {
        int i = chunk * 32 + lane;
        int v = cls_ids[i];
        unsigned m = __ballot_sync(0xffffffffu, v == w);
        if (v == w) {
            int rank = __popc(m & ((1u << lane) - 1));
            g_cls_list[w][base + rank] = i;
        }
        base += __popc(m);
    }
    if (lane == 0) g_cls_count[w] = base;
}

// One CTA per (class, feature, hi-tile). Tile-constant weights / neighbor
// indices / bias_high live in registers; loop over the class's samples with
// prefetched x staging and a double-buffered shared y tile (1 sync / sample).
__global__ void __launch_bounds__(THREADS_, 3)
upsample_kernel(const float* __restrict__ x,
                const int*   __restrict__ nbr,
                const float* __restrict__ wmap,
                const float* __restrict__ blo,
                const float* __restrict__ bhi,
                float*       __restrict__ out)
{
    __shared__ float y_sh[2][P_LO_];

    const int tile = blockIdx.x;
    const int f    = blockIdx.y;
    const int c    = blockIdx.z;
    const int n    = g_cls_count[c];
    if (n == 0) return;                       // block-uniform exit (before syncs)

    const int tid = threadIdx.x;
    const int p0  = tile * TILE_ + tid * PPT_;

    // ---- tile-constant loads (once per CTA, coalesced float2/int2) ----
    // 18 consecutive floats (p0 even -> 8B aligned): linear wv[j], j in [0,18)
    // wv[k]   = w[p0][k],  wv[9+k] = w[p0+1][k]
    const float2* wp = reinterpret_cast<const float2*>(
        wmap + (((size_t)c * NF_ + f) * P_HI_ + (size_t)p0) * K_);
    float wv[2 * K_];
    #pragma unroll
    for (int i = 0; i < K_; i++) {
        float2 v = wp[i];
        wv[2 * i] = v.x; wv[2 * i + 1] = v.y;
    }

    const int2* ip = reinterpret_cast<const int2*>(nbr + (size_t)p0 * K_);
    int nb[2 * K_];
    #pragma unroll
    for (int i = 0; i < K_; i++) {
        int2 v = ip[i];
        nb[2 * i] = v.x; nb[2 * i + 1] = v.y;
    }

    const float2 bh = *reinterpret_cast<const float2*>(
        bhi + ((size_t)c * NF_ + f) * P_HI_ + p0);

    // bias_low slice for this (c,f): loop-invariant, one float4 per thread.
    const float4 bv = reinterpret_cast<const float4*>(
        blo + ((size_t)c * NF_ + f) * P_LO_)[tid];

    // prefetch first sample's x
    int b = g_cls_list[c][0];
    float4 xv = reinterpret_cast<const float4*>(
        x + (size_t)b * (NF_ * P_LO_) + (size_t)f * P_LO_)[tid];

    for (int s = 0; s < n; s++) {
        float* buf = y_sh[s & 1];
        reinterpret_cast<float4*>(buf)[tid] =
            make_float4(xv.x - bv.x, xv.y - bv.y, xv.z - bv.z, xv.w - bv.w);

        const int b_cur = b;
        if (s + 1 < n) {                       // prefetch next sample's x
            b = g_cls_list[c][s + 1];
            xv = reinterpret_cast<const float4*>(
                x + (size_t)b * (NF_ * P_LO_) + (size_t)f * P_LO_)[tid];
        }

        __syncthreads();                       // staging visible; prev compute done

        float s0 = bh.x, s1 = bh.y;
        #pragma unroll
        for (int k = 0; k < K_; k++) {
            s0 = fmaf(wv[k],      buf[nb[k]],      s0);
            s1 = fmaf(wv[K_ + k], buf[nb[K_ + k]], s1);
        }

        *reinterpret_cast<float2*>(
            out + ((size_t)b_cur * NF_ + f) * P_HI_ + p0) = make_float2(s0, s1);
        // no trailing sync: next iter writes the other buffer; the sync at
        // iter s+1 orders this iter's reads before iter s+2's overwrite.
    }
}

extern "C" void kernel_launch(void* const* d_in, const int* in_sizes, int n_in,
                              void* d_out, int out_size) {
    const float* x    = (const float*)d_in[0];   // (BS, NF*P_LO) f32
    const int*   cls  = (const int*)  d_in[1];   // (BS,) i32
    const int*   nbr  = (const int*)  d_in[2];   // (P_HI, K) i32
    const float* wmap = (const float*)d_in[3];   // (NC, NF, P_HI, K) f32
    const float* blo  = (const float*)d_in[4];   // (NC, NF, P_LO) f32
    const float* bhi  = (const float*)d_in[5];   // (NC, NF, P_HI) f32
    float* out = (float*)d_out;                  // (BS, NF, P_HI) f32

    build_lists_kernel<<<2, 576>>>(cls);         // 36 warps, one per class
    dim3 grid(NTILES_, NF_, NC_);
    upsample_kernel<<<grid, THREADS_>>>(x, nbr, wmap, blo, bhi, out);
}